// round 1
// baseline (speedup 1.0000x reference)
#include <cuda_runtime.h>
#include <cstdint>

// y[8192,4096] = x[8192,4096] @ W[4096,4096]^T + bias   (all fp32)
// Strategy R0: TF32 mma.sync GEMM. Pre-round inputs to TF32 (rna) into
// __device__ scratch; classic double-buffered cp.async mainloop.

#define MDIM 8192
#define NDIM 4096
#define KDIM 4096

#define BM 128
#define BN 128
#define BK 32
#define PAD_LD 36                 // floats per smem row: 4g+t bank pattern, conflict-free
#define A_STAGE (BM * PAD_LD)
#define B_STAGE (BN * PAD_LD)
#define SMEM_FLOATS (2 * A_STAGE + 2 * B_STAGE + BN)
#define SMEM_BYTES (SMEM_FLOATS * 4)

// Scratch for TF32-rounded operands (allocation-free rule: __device__ globals).
__device__ float g_x[(size_t)MDIM * KDIM];   // 128 MB
__device__ float g_w[(size_t)NDIM * KDIM];   //  64 MB

// ---------------------------------------------------------------------------
// TF32 pre-rounding (round-to-nearest keeps the dot-product bias ~2^-13
// instead of truncation's ~2^-11 one-sided bias)
// ---------------------------------------------------------------------------
__device__ __forceinline__ float rna_tf32(float x) {
    uint32_t r;
    asm("cvt.rna.tf32.f32 %0, %1;" : "=r"(r) : "f"(x));
    return __uint_as_float(r);
}

__global__ void cvt_tf32_kernel(const float4* __restrict__ in,
                                float4* __restrict__ out, int n4) {
    int i = blockIdx.x * blockDim.x + threadIdx.x;
    if (i >= n4) return;
    float4 v = in[i];
    v.x = rna_tf32(v.x);
    v.y = rna_tf32(v.y);
    v.z = rna_tf32(v.z);
    v.w = rna_tf32(v.w);
    out[i] = v;
}

// ---------------------------------------------------------------------------
// cp.async helpers
// ---------------------------------------------------------------------------
__device__ __forceinline__ void cp_async16(void* smem_ptr, const void* gptr) {
    uint32_t sa = (uint32_t)__cvta_generic_to_shared(smem_ptr);
    asm volatile("cp.async.cg.shared.global [%0], [%1], 16;\n" ::"r"(sa), "l"(gptr));
}
#define CP_COMMIT() asm volatile("cp.async.commit_group;\n" ::: "memory")
#define CP_WAIT0()  asm volatile("cp.async.wait_group 0;\n" ::: "memory")

__device__ __forceinline__ void load_tile(float* sA_, float* sB_,
                                          const float* gA, const float* gB,
                                          int kt, int tid) {
    int k0 = kt * BK;
#pragma unroll
    for (int j = 0; j < 4; j++) {
        int idx = tid + j * 256;        // 0..1023 : 128 rows x 8 float4
        int row = idx >> 3;
        int c4  = idx & 7;
        // row stride 36 floats = 144 B (multiple of 16) -> cp.async 16B aligned
        cp_async16(sA_ + row * PAD_LD + c4 * 4, gA + (size_t)row * KDIM + k0 + c4 * 4);
        cp_async16(sB_ + row * PAD_LD + c4 * 4, gB + (size_t)row * KDIM + k0 + c4 * 4);
    }
}

// ---------------------------------------------------------------------------
// TF32 GEMM: 128x128x32 CTA tile, 8 warps (2x4), warp tile 64x32,
// m16n8k8 tf32 mma.sync, double-buffered cp.async.
// ---------------------------------------------------------------------------
__global__ __launch_bounds__(256, 2)
void gemm_tf32_kernel(const float* __restrict__ bias, float* __restrict__ out) {
    extern __shared__ float smem[];
    float* sA = smem;
    float* sB = smem + 2 * A_STAGE;
    float* sBias = smem + 2 * A_STAGE + 2 * B_STAGE;

    const int tid  = threadIdx.x;
    const int lane = tid & 31;
    const int warp = tid >> 5;
    const int wm = warp >> 2;   // 0..1
    const int wn = warp & 3;    // 0..3
    const int g = lane >> 2;    // 0..7
    const int t = lane & 3;     // 0..3

    const int blockN = blockIdx.x * BN;
    const int blockM = blockIdx.y * BM;

    const float* gA = g_x + (size_t)blockM * KDIM;
    const float* gB = g_w + (size_t)blockN * KDIM;

    if (tid < BN) sBias[tid] = bias[blockN + tid];

    float acc[4][4][4];
#pragma unroll
    for (int i = 0; i < 4; i++)
#pragma unroll
        for (int j = 0; j < 4; j++)
#pragma unroll
            for (int r = 0; r < 4; r++) acc[i][j][r] = 0.0f;

    // prologue: stage tile 0
    load_tile(sA, sB, gA, gB, 0, tid);
    CP_COMMIT();

    const int NK = KDIM / BK;   // 128
    for (int kt = 0; kt < NK; kt++) {
        const int cur = kt & 1;
        CP_WAIT0();
        __syncthreads();
        if (kt + 1 < NK) {
            const int nxt = cur ^ 1;
            load_tile(sA + nxt * A_STAGE, sB + nxt * B_STAGE, gA, gB, kt + 1, tid);
            CP_COMMIT();
        }
        const float* As_ = sA + cur * A_STAGE;
        const float* Bs_ = sB + cur * B_STAGE;

#pragma unroll
        for (int kk = 0; kk < 4; kk++) {
            const int k0 = kk * 8;
            uint32_t a[4][4], b[4][2];
#pragma unroll
            for (int mt = 0; mt < 4; mt++) {
                int r = wm * 64 + mt * 16 + g;
                a[mt][0] = __float_as_uint(As_[r * PAD_LD + k0 + t]);
                a[mt][1] = __float_as_uint(As_[(r + 8) * PAD_LD + k0 + t]);
                a[mt][2] = __float_as_uint(As_[r * PAD_LD + k0 + t + 4]);
                a[mt][3] = __float_as_uint(As_[(r + 8) * PAD_LD + k0 + t + 4]);
            }
#pragma unroll
            for (int nt = 0; nt < 4; nt++) {
                int c = wn * 32 + nt * 8 + g;
                b[nt][0] = __float_as_uint(Bs_[c * PAD_LD + k0 + t]);
                b[nt][1] = __float_as_uint(Bs_[c * PAD_LD + k0 + t + 4]);
            }
#pragma unroll
            for (int mt = 0; mt < 4; mt++)
#pragma unroll
                for (int nt = 0; nt < 4; nt++) {
                    asm volatile(
                        "mma.sync.aligned.m16n8k8.row.col.f32.tf32.tf32.f32 "
                        "{%0,%1,%2,%3}, {%4,%5,%6,%7}, {%8,%9}, {%0,%1,%2,%3};\n"
                        : "+f"(acc[mt][nt][0]), "+f"(acc[mt][nt][1]),
                          "+f"(acc[mt][nt][2]), "+f"(acc[mt][nt][3])
                        : "r"(a[mt][0]), "r"(a[mt][1]), "r"(a[mt][2]), "r"(a[mt][3]),
                          "r"(b[nt][0]), "r"(b[nt][1]));
                }
        }
        __syncthreads();
    }

    // epilogue: bias add + fp32 store (float2 per fragment row)
#pragma unroll
    for (int mt = 0; mt < 4; mt++) {
        int r0 = blockM + wm * 64 + mt * 16 + g;
#pragma unroll
        for (int nt = 0; nt < 4; nt++) {
            int cl = wn * 32 + nt * 8 + 2 * t;
            int c = blockN + cl;
            float b0 = sBias[cl], b1 = sBias[cl + 1];
            float2 v0 = make_float2(acc[mt][nt][0] + b0, acc[mt][nt][1] + b1);
            float2 v1 = make_float2(acc[mt][nt][2] + b0, acc[mt][nt][3] + b1);
            *reinterpret_cast<float2*>(out + (size_t)r0 * NDIM + c) = v0;
            *reinterpret_cast<float2*>(out + (size_t)(r0 + 8) * NDIM + c) = v1;
        }
    }
}

// ---------------------------------------------------------------------------
extern "C" void kernel_launch(void* const* d_in, const int* in_sizes, int n_in,
                              void* d_out, int out_size) {
    const float* x    = (const float*)d_in[0];   // [8192,4096]
    const float* w    = (const float*)d_in[1];   // [4096,4096]
    const float* bias = (const float*)d_in[2];   // [4096]
    float* y = (float*)d_out;                    // [8192,4096]

    void* gx_ptr = nullptr;
    void* gw_ptr = nullptr;
    cudaGetSymbolAddress(&gx_ptr, g_x);
    cudaGetSymbolAddress(&gw_ptr, g_w);

    const int n4x = MDIM * KDIM / 4;
    const int n4w = NDIM * KDIM / 4;
    cvt_tf32_kernel<<<(n4x + 255) / 256, 256>>>((const float4*)x, (float4*)gx_ptr, n4x);
    cvt_tf32_kernel<<<(n4w + 255) / 256, 256>>>((const float4*)w, (float4*)gw_ptr, n4w);

    cudaFuncSetAttribute(gemm_tf32_kernel,
                         cudaFuncAttributeMaxDynamicSharedMemorySize, SMEM_BYTES);
    dim3 grid(NDIM / BN, MDIM / BM);   // 32 x 64
    gemm_tf32_kernel<<<grid, 256, SMEM_BYTES>>>(bias, y);
}

// round 3
// speedup vs baseline: 1.1321x; 1.1321x over previous
#include <cuda_runtime.h>
#include <cstdint>

// y[8192,4096] = x[8192,4096] @ W[4096,4096]^T + bias  (fp32)
// R2: TF32 mma.sync GEMM + 16x16 block-sparsity skip (50% of W blocks are
// exactly zero). tcgen05 is unavailable: harness PTX targets sm_103 (no 'a').
// CTA tile 128x256, warp tile 64x64, BK=32, double-buffered cp.async.
// Zero blocks: skip mma groups (16 mma each) AND skip their B cp.async loads.

#define MDIM 8192
#define NDIM 4096
#define KDIM 4096

#define BM 128
#define BN 256
#define BK 32
#define PAD_LD 36                       // 144B rows: 16B-aligned, conflict-free
#define A_STAGE (BM * PAD_LD)           // 4608 floats
#define B_STAGE (BN * PAD_LD)           // 9216 floats
#define SM_BIAS_OFF (2 * A_STAGE + 2 * B_STAGE)        // floats
#define SM_MASK_OFF (SM_BIAS_OFF + BN)                 // floats (reinterp as u32)
#define SMEM_FLOATS (SM_MASK_OFF + 128)
#define SMEM_BYTES (SMEM_FLOATS * 4)

#define NB_O (NDIM / 16)                // 256 o-blocks
#define NB_I (KDIM / 16)                // 256 i-blocks

__device__ float g_x[(size_t)MDIM * KDIM];       // tf32-rounded x
__device__ float g_w[(size_t)NDIM * KDIM];       // tf32-rounded w
__device__ uint32_t g_mask[NB_O * 8];            // [ob][8 words of 32 ib-bits]

// ---------------------------------------------------------------------------
// TF32 pre-rounding
// ---------------------------------------------------------------------------
__device__ __forceinline__ float rna_tf32(float x) {
    uint32_t r;
    asm("cvt.rna.tf32.f32 %0, %1;" : "=r"(r) : "f"(x));
    return __uint_as_float(r);
}

__global__ void cvt_tf32_kernel(const float4* __restrict__ in,
                                float4* __restrict__ out, int n4) {
    int i = blockIdx.x * blockDim.x + threadIdx.x;
    if (i >= n4) return;
    float4 v = in[i];
    v.x = rna_tf32(v.x); v.y = rna_tf32(v.y);
    v.z = rna_tf32(v.z); v.w = rna_tf32(v.w);
    out[i] = v;
}

// ---------------------------------------------------------------------------
// Block-nonzero mask: one CTA per o-block row, one thread per i-block.
// ---------------------------------------------------------------------------
__global__ void mask_kernel(const float* __restrict__ w) {
    int ob = blockIdx.x;          // 0..255
    int ib = threadIdx.x;         // 0..255
    const float* base = w + (size_t)(ob * 16) * KDIM + ib * 16;
    bool nz = false;
#pragma unroll
    for (int r = 0; r < 16; r++) {
        const float4* p = reinterpret_cast<const float4*>(base + (size_t)r * KDIM);
#pragma unroll
        for (int c = 0; c < 4; c++) {
            float4 v = p[c];
            nz |= (v.x != 0.0f) | (v.y != 0.0f) | (v.z != 0.0f) | (v.w != 0.0f);
        }
    }
    uint32_t bal = __ballot_sync(0xffffffffu, nz);
    if ((ib & 31) == 0) g_mask[ob * 8 + (ib >> 5)] = bal;
}

// ---------------------------------------------------------------------------
// cp.async helpers
// ---------------------------------------------------------------------------
__device__ __forceinline__ void cp_async16(uint32_t sa, const void* gptr) {
    asm volatile("cp.async.cg.shared.global [%0], [%1], 16;\n" ::"r"(sa), "l"(gptr));
}
#define CP_COMMIT() asm volatile("cp.async.commit_group;\n" ::: "memory")
#define CP_WAIT0()  asm volatile("cp.async.wait_group 0;\n" ::: "memory")

// A: 128 rows x 32 floats. B: 256 rows x 32 floats, zero-block chunks skipped.
__device__ __forceinline__ void load_stage(uint32_t sA_u, uint32_t sB_u,
                                           const float* gA, const float* gB,
                                           int kt, int tid,
                                           const uint32_t* sMask) {
    const int koff = kt * BK;
    const int c = tid & 7;
    const int r0 = tid >> 3;
#pragma unroll
    for (int j = 0; j < 4; j++) {                    // A: 4 chunks/thread
        int row = r0 + j * 32;
        cp_async16(sA_u + (row * PAD_LD + c * 4) * 4,
                   gA + (size_t)row * KDIM + koff + c * 4);
    }
    const int ib = 2 * kt + (c >> 2);
    const int wsel = ib >> 5;
    const int bsel = ib & 31;
#pragma unroll
    for (int j = 0; j < 8; j++) {                    // B: 8 chunks/thread
        int row = r0 + j * 32;
        int obl = row >> 4;                          // 0..15
        uint32_t mword = sMask[obl * 8 + wsel];
        if ((mword >> bsel) & 1u) {
            cp_async16(sB_u + (row * PAD_LD + c * 4) * 4,
                       gB + (size_t)row * KDIM + koff + c * 4);
        }
    }
}

// ---------------------------------------------------------------------------
// GEMM: CTA 128x256, 8 warps as 2(M) x 4(N), warp tile 64x64 (mt=4, nt=8)
// ---------------------------------------------------------------------------
__global__ __launch_bounds__(256, 1)
void gemm_tf32_sparse(const float* __restrict__ bias, float* __restrict__ out) {
    extern __shared__ float smem[];
    float* sA = smem;
    float* sB = smem + 2 * A_STAGE;
    float* sBias = smem + SM_BIAS_OFF;
    uint32_t* sMask = reinterpret_cast<uint32_t*>(smem + SM_MASK_OFF);
    const uint32_t sA_u = (uint32_t)__cvta_generic_to_shared(sA);
    const uint32_t sB_u = (uint32_t)__cvta_generic_to_shared(sB);

    const int tid  = threadIdx.x;
    const int lane = tid & 31;
    const int warp = tid >> 5;
    const int wm = warp >> 2;        // 0..1
    const int wn = warp & 3;         // 0..3
    const int g = lane >> 2;
    const int t = lane & 3;

    const int bn = blockIdx.x * BN;
    const int bm = blockIdx.y * BM;

    sBias[tid] = bias[bn + tid];
    if (tid < 128) sMask[tid] = g_mask[(bn >> 1) + tid];   // 16 ob rows x 8 words
    __syncthreads();

    const float* gA = g_x + (size_t)bm * KDIM;
    const float* gB = g_w + (size_t)bn * KDIM;

    float acc[4][8][4];
#pragma unroll
    for (int i = 0; i < 4; i++)
#pragma unroll
        for (int j = 0; j < 8; j++)
#pragma unroll
            for (int r = 0; r < 4; r++) acc[i][j][r] = 0.0f;

    load_stage(sA_u, sB_u, gA, gB, 0, tid, sMask);
    CP_COMMIT();

    uint32_t mw[4];                  // mask words for this warp's 4 o-blocks
    const int NKT = KDIM / BK;       // 128

    for (int kt = 0; kt < NKT; kt++) {
        const int cur = kt & 1;
        CP_WAIT0();
        __syncthreads();
        if (kt + 1 < NKT) {
            const int nxt = cur ^ 1;
            load_stage(sA_u + nxt * A_STAGE * 4, sB_u + nxt * B_STAGE * 4,
                       gA, gB, kt + 1, tid, sMask);
        }
        CP_COMMIT();

        if ((kt & 15) == 0) {
#pragma unroll
            for (int q = 0; q < 4; q++)
                mw[q] = sMask[(wn * 4 + q) * 8 + (kt >> 4)];
        }
        const int bbase = (kt & 15) * 2;

        const float* As_ = sA + cur * A_STAGE;
        const float* Bs_ = sB + cur * B_STAGE;

#pragma unroll
        for (int h = 0; h < 2; h++) {                 // i-block half of this tile
            uint32_t a[2][4][4];
#pragma unroll
            for (int kk2 = 0; kk2 < 2; kk2++) {
                const int k0 = (h * 2 + kk2) * 8;
#pragma unroll
                for (int mt = 0; mt < 4; mt++) {
                    int r = wm * 64 + mt * 16 + g;
                    a[kk2][mt][0] = __float_as_uint(As_[r * PAD_LD + k0 + t]);
                    a[kk2][mt][1] = __float_as_uint(As_[(r + 8) * PAD_LD + k0 + t]);
                    a[kk2][mt][2] = __float_as_uint(As_[r * PAD_LD + k0 + t + 4]);
                    a[kk2][mt][3] = __float_as_uint(As_[(r + 8) * PAD_LD + k0 + t + 4]);
                }
            }
#pragma unroll
            for (int q = 0; q < 4; q++) {             // o-block within warp tile
                if ((mw[q] >> (bbase + h)) & 1u) {
#pragma unroll
                    for (int kk2 = 0; kk2 < 2; kk2++) {
                        const int k0 = (h * 2 + kk2) * 8;
#pragma unroll
                        for (int nt2 = 0; nt2 < 2; nt2++) {
                            const int nt = q * 2 + nt2;
                            const int ccol = wn * 64 + nt * 8 + g;
                            uint32_t b0 = __float_as_uint(Bs_[ccol * PAD_LD + k0 + t]);
                            uint32_t b1 = __float_as_uint(Bs_[ccol * PAD_LD + k0 + t + 4]);
#pragma unroll
                            for (int mt = 0; mt < 4; mt++) {
                                asm volatile(
                                    "mma.sync.aligned.m16n8k8.row.col.f32.tf32.tf32.f32 "
                                    "{%0,%1,%2,%3}, {%4,%5,%6,%7}, {%8,%9}, {%0,%1,%2,%3};\n"
                                    : "+f"(acc[mt][nt][0]), "+f"(acc[mt][nt][1]),
                                      "+f"(acc[mt][nt][2]), "+f"(acc[mt][nt][3])
                                    : "r"(a[kk2][mt][0]), "r"(a[kk2][mt][1]),
                                      "r"(a[kk2][mt][2]), "r"(a[kk2][mt][3]),
                                      "r"(b0), "r"(b1));
                            }
                        }
                    }
                }
            }
        }
        __syncthreads();
    }

    // epilogue: bias add + fp32 store
#pragma unroll
    for (int mt = 0; mt < 4; mt++) {
        int r0 = bm + wm * 64 + mt * 16 + g;
#pragma unroll
        for (int nt = 0; nt < 8; nt++) {
            int cl = wn * 64 + nt * 8 + 2 * t;
            int c = bn + cl;
            float b0 = sBias[cl], b1 = sBias[cl + 1];
            float2 v0 = make_float2(acc[mt][nt][0] + b0, acc[mt][nt][1] + b1);
            float2 v1 = make_float2(acc[mt][nt][2] + b0, acc[mt][nt][3] + b1);
            *reinterpret_cast<float2*>(out + (size_t)r0 * NDIM + c) = v0;
            *reinterpret_cast<float2*>(out + (size_t)(r0 + 8) * NDIM + c) = v1;
        }
    }
}

// ---------------------------------------------------------------------------
extern "C" void kernel_launch(void* const* d_in, const int* in_sizes, int n_in,
                              void* d_out, int out_size) {
    const float* x    = (const float*)d_in[0];   // [8192,4096]
    const float* w    = (const float*)d_in[1];   // [4096,4096]
    const float* bias = (const float*)d_in[2];   // [4096]
    float* y = (float*)d_out;                    // [8192,4096]

    void* gx_ptr = nullptr;
    void* gw_ptr = nullptr;
    cudaGetSymbolAddress(&gx_ptr, g_x);
    cudaGetSymbolAddress(&gw_ptr, g_w);

    mask_kernel<<<NB_O, 256>>>(w);

    const int n4x = MDIM * KDIM / 4;
    const int n4w = NDIM * KDIM / 4;
    cvt_tf32_kernel<<<(n4x + 255) / 256, 256>>>((const float4*)x, (float4*)gx_ptr, n4x);
    cvt_tf32_kernel<<<(n4w + 255) / 256, 256>>>((const float4*)w, (float4*)gw_ptr, n4w);

    cudaFuncSetAttribute(gemm_tf32_sparse,
                         cudaFuncAttributeMaxDynamicSharedMemorySize, SMEM_BYTES);
    dim3 grid(NDIM / BN, MDIM / BM);   // 16 x 64
    gemm_tf32_sparse<<<grid, 256, SMEM_BYTES>>>(bias, y);
}